// round 1
// baseline (speedup 1.0000x reference)
#include <cuda_runtime.h>
#include <cstdint>

#define NH    218
#define NSUB  47524      // 218*218
#define NROWS 64         // B * C_OUT * C_IN = 2*8*4

// ---------------- device globals (no allocations allowed) ----------------
__device__ float2   g_Wn[8][4][12][24];   // [-2*W] paired over (p=2pp, p=2pp+1)
__device__ float    g_c2[8][4];           // ||Kp||^2+||Rp||^2+||Cp||^2 (perm-invariant)
__device__ unsigned g_rowmax_u[NROWS];
__device__ float    g_rowmax_f[NROWS];
__device__ float    g_rowsum[NROWS];
__device__ float    g_sims[(size_t)NROWS * NSUB];   // 12.2 MB scratch

__constant__ unsigned char c_P[24][4] = {
  {0,1,2,3},{0,1,3,2},{0,2,1,3},{0,2,3,1},{0,3,1,2},{0,3,2,1},
  {1,0,2,3},{1,0,3,2},{1,2,0,3},{1,2,3,0},{1,3,0,2},{1,3,2,0},
  {2,0,1,3},{2,0,3,1},{2,1,0,3},{2,1,3,0},{2,3,0,1},{2,3,1,0},
  {3,0,1,2},{3,0,2,1},{3,1,0,2},{3,1,2,0},{3,2,0,1},{3,2,1,0}
};

// ---------------- prep: expand permuted weights, init reductions ----------
__global__ void prep_kernel(const float* __restrict__ ks,
                            const float* __restrict__ kr,
                            const float* __restrict__ kc) {
    int tid = threadIdx.x;
    if (tid < NROWS) { g_rowmax_u[tid] = 0u; g_rowsum[tid] = 0.0f; }
    if (tid < 32) {
        int oi = tid;
        float s = 0.0f;
        const float* a = ks + oi * 16;
        #pragma unroll
        for (int j = 0; j < 16; j++) s += a[j] * a[j];
        const float* r = kr + oi * 4;
        const float* c = kc + oi * 4;
        #pragma unroll
        for (int j = 0; j < 4; j++) { s += r[j] * r[j]; s += c[j] * c[j]; }
        ((float*)g_c2)[oi] = s;
    }
    // 8*4*24 perms * 24 components = 18432 weight entries
    for (int e = tid; e < 8 * 4 * 24 * 24; e += blockDim.x) {
        int c  = e % 24;
        int t  = e / 24;
        int p  = t % 24;
        int oi = t / 24;
        float val;
        if (c < 16) {
            int a = c >> 2, bb = c & 3;
            val = ks[oi * 16 + (int)c_P[p][a] * 4 + (int)c_P[p][bb]];
        } else if (c < 20) {
            val = kr[oi * 4 + (int)c_P[p][c - 16]];
        } else {
            val = kc[oi * 4 + (int)c_P[p][c - 20]];
        }
        // g_Wn[o][i][p>>1][c], component (p&1), holds -2*val
        ((float*)g_Wn)[(oi * 12 + (p >> 1)) * 48 + c * 2 + (p & 1)] = -2.0f * val;
    }
}

// ---------------- h_mean: closed form over feature weights ----------------
__global__ void hmean_kernel(const float* __restrict__ feats, float* __restrict__ out) {
    int b = blockIdx.x, f = threadIdx.x;
    float acc = 0.0f;
    for (int n = 0; n < 224; n++) {
        int lo = (n >= NH) ? ((n - (NH - 2)) >> 1) : 0;   // ceil((n-217)/2)
        int hi = min(3, n >> 1);
        float w = (float)(hi - lo + 1);
        acc += w * feats[(b * 224 + n) * 128 + f];
    }
    out[b * 128 + f] = acc * (2.0f / (float)NH);
}

// ---------------- sims: packed-f32x2 distance + min over perms ------------
__global__ void __launch_bounds__(256, 2)
sims_kernel(const float* __restrict__ graph, const float* __restrict__ types) {
    __shared__ __align__(16) float2 sw[4][4][12][24];  // [oLocal][i][pp][c]
    __shared__ float    sc2[16];
    __shared__ unsigned smax[NROWS];

    int tid   = threadIdx.x;
    int b     = blockIdx.y;
    int oBase = blockIdx.z * 4;

    {
        const float2* src = ((const float2*)g_Wn) + (size_t)oBase * 4 * 12 * 24;
        float2* dst = &sw[0][0][0][0];
        for (int e = tid; e < 4 * 4 * 12 * 24; e += 256) dst[e] = src[e];
        if (tid < 16) sc2[tid] = ((const float*)g_c2)[oBase * 4 + tid];
        if (tid < NROWS) smax[tid] = 0u;
    }
    __syncthreads();

    int  s     = blockIdx.x * 256 + tid;
    bool valid = s < NSUB;
    int  scl   = valid ? s : (NSUB - 1);
    int  h1    = scl / NH;
    int  h2    = scl - h1 * NH;

    #pragma unroll 1
    for (int i = 0; i < 4; i++) {
        // gather x = [sub(16) | row_types(4) | col_types(4)]
        float xv[24];
        const float* gp = graph + (((b * 4 + i) * 224) + h1) * 224 + h2;
        #pragma unroll
        for (int a = 0; a < 4; a++) {
            const float* rp = gp + (2 * a) * 224;
            #pragma unroll
            for (int bb = 0; bb < 4; bb++) xv[a * 4 + bb] = rp[2 * bb];
        }
        const float* tp = types + (b * 4 + i) * 224;
        #pragma unroll
        for (int a = 0; a < 4; a++) {
            xv[16 + a] = tp[h1 + 2 * a];
            xv[20 + a] = tp[h2 + 2 * a];
        }
        float x2 = 0.0f;
        #pragma unroll
        for (int c = 0; c < 24; c++) x2 = fmaf(xv[c], xv[c], x2);

        // duplicate x into packed f32x2 registers
        unsigned long long xd[24];
        #pragma unroll
        for (int c = 0; c < 24; c++) {
            unsigned u = __float_as_uint(xv[c]);
            asm("mov.b64 %0, {%1, %2};" : "=l"(xd[c]) : "r"(u), "r"(u));
        }

        #pragma unroll 1
        for (int o = 0; o < 4; o++) {
            float initf = sc2[o * 4 + i] + x2;
            unsigned long long init;
            {
                unsigned u = __float_as_uint(initf);
                asm("mov.b64 %0, {%1, %2};" : "=l"(init) : "r"(u), "r"(u));
            }
            float m = 3.4e38f;
            const ulonglong2* wbase = (const ulonglong2*)&sw[o][i][0][0];
            #pragma unroll
            for (int pp = 0; pp < 12; pp += 2) {
                unsigned long long acc0 = init, acc1 = init;
                const ulonglong2* w0 = wbase + pp * 12;
                const ulonglong2* w1 = wbase + (pp + 1) * 12;
                #pragma unroll
                for (int cc = 0; cc < 12; cc++) {
                    ulonglong2 wa = w0[cc];
                    ulonglong2 wb = w1[cc];
                    asm("fma.rn.f32x2 %0, %1, %2, %0;" : "+l"(acc0) : "l"(xd[2*cc]),   "l"(wa.x));
                    asm("fma.rn.f32x2 %0, %1, %2, %0;" : "+l"(acc0) : "l"(xd[2*cc+1]), "l"(wa.y));
                    asm("fma.rn.f32x2 %0, %1, %2, %0;" : "+l"(acc1) : "l"(xd[2*cc]),   "l"(wb.x));
                    asm("fma.rn.f32x2 %0, %1, %2, %0;" : "+l"(acc1) : "l"(xd[2*cc+1]), "l"(wb.y));
                }
                float l0, h0, l1, hh1;
                asm("mov.b64 {%0, %1}, %2;" : "=f"(l0), "=f"(h0)  : "l"(acc0));
                asm("mov.b64 {%0, %1}, %2;" : "=f"(l1), "=f"(hh1) : "l"(acc1));
                m = fminf(m, fminf(fminf(l0, h0), fminf(l1, hh1)));
            }

            int row = b * 32 + (oBase + o) * 4 + i;
            if (valid) g_sims[(size_t)row * NSUB + s] = m;
            unsigned key = 0u;
            if (valid) {
                unsigned u = __float_as_uint(m);
                key = (u & 0x80000000u) ? ~u : (u | 0x80000000u);
            }
            unsigned kw = __reduce_max_sync(0xffffffffu, key);
            if ((tid & 31) == 0) atomicMax(&smax[row], kw);
        }
    }

    __syncthreads();
    if (tid < NROWS && smax[tid]) atomicMax(&g_rowmax_u[tid], smax[tid]);
}

// ---------------- softmax passes -----------------------------------------
__global__ void finmax_kernel() {
    int t = threadIdx.x;
    if (t < NROWS) {
        unsigned u = g_rowmax_u[t];
        g_rowmax_f[t] = (u & 0x80000000u) ? __uint_as_float(u & 0x7fffffffu)
                                          : __uint_as_float(~u);
    }
}

__global__ void sumexp_kernel() {
    int row = blockIdx.y;
    float mx = g_rowmax_f[row];
    const float* sp = g_sims + (size_t)row * NSUB;
    float acc = 0.0f;
    int base = blockIdx.x * (256 * 8) + threadIdx.x;
    #pragma unroll
    for (int j = 0; j < 8; j++) {
        int s = base + j * 256;
        if (s < NSUB) acc += __expf(sp[s] - mx);
    }
    #pragma unroll
    for (int off = 16; off; off >>= 1) acc += __shfl_xor_sync(0xffffffffu, acc, off);
    __shared__ float ws[8];
    if ((threadIdx.x & 31) == 0) ws[threadIdx.x >> 5] = acc;
    __syncthreads();
    if (threadIdx.x < 8) {
        float v = ws[threadIdx.x];
        #pragma unroll
        for (int off = 4; off; off >>= 1) v += __shfl_xor_sync(0xffu, v, off);
        if (threadIdx.x == 0) atomicAdd(&g_rowsum[row], v);
    }
}

__global__ void writeout_kernel(float* __restrict__ out) {
    int row = blockIdx.y;
    float mx  = g_rowmax_f[row];
    float inv = 1.0f / g_rowsum[row];
    const float* sp = g_sims + (size_t)row * NSUB;
    float* op = out + 256 + (size_t)row * NSUB;
    int base = blockIdx.x * (256 * 4) + threadIdx.x;
    #pragma unroll
    for (int j = 0; j < 4; j++) {
        int s = base + j * 256;
        if (s < NSUB)
            op[s] = (1.0f - __expf(sp[s] - mx) * inv) * (1.0f / (float)NSUB);
    }
}

// ---------------- launch ---------------------------------------------------
extern "C" void kernel_launch(void* const* d_in, const int* in_sizes, int n_in,
                              void* d_out, int out_size) {
    const float* graph    = (const float*)d_in[0];
    const float* types    = (const float*)d_in[1];
    const float* features = (const float*)d_in[2];
    const float* ks       = (const float*)d_in[3];
    const float* kr       = (const float*)d_in[4];
    const float* kc       = (const float*)d_in[5];
    float* out = (float*)d_out;

    prep_kernel<<<1, 256>>>(ks, kr, kc);
    hmean_kernel<<<2, 128>>>(features, out);
    sims_kernel<<<dim3((NSUB + 255) / 256, 2, 2), 256>>>(graph, types);
    finmax_kernel<<<1, 64>>>();
    sumexp_kernel<<<dim3((NSUB + 2047) / 2048, NROWS), 256>>>();
    writeout_kernel<<<dim3((NSUB + 1023) / 1024, NROWS), 256>>>(out);
}